// round 6
// baseline (speedup 1.0000x reference)
#include <cuda_runtime.h>
#include <cstdint>
#include <cfloat>
#include <math.h>

typedef unsigned long long u64;

#define DHALF 64
#define DFULL 128
#define KCODES 512
#define MTILE 64
#define ZS_STRIDE 66   // float2 per z row (padded for bank-conflict-free LDS)

// Scratch accumulators (device globals: allocation-free per harness rules)
__device__ float g_nt[KCODES];
__device__ float g_dw[KCODES * DFULL];
__device__ float g_ysq[KCODES];

__device__ __forceinline__ u64 fma2(u64 a, u64 b, u64 c) {
    u64 d;
    asm("fma.rn.f32x2 %0, %1, %2, %3;" : "=l"(d) : "l"(a), "l"(b), "l"(c));
    return d;
}

// ---------------------------------------------------------------------------
// Stage 0: y_sq[k] = sum_j w[k][j]^2, zero count + dw accumulators.
// ---------------------------------------------------------------------------
__global__ void vq_prep(const float* __restrict__ emb) {
    int k = blockIdx.x * blockDim.x + threadIdx.x;
    if (k < KCODES) {
        const float* w = emb + (size_t)k * DFULL;
        float s = 0.f;
        #pragma unroll 8
        for (int d = 0; d < DFULL; d++) s = __fadd_rn(s, __fmul_rn(w[d], w[d]));
        g_ysq[k] = s;
        g_nt[k] = 0.f;
        #pragma unroll 8
        for (int d = 0; d < DFULL; d++) g_dw[(size_t)k * DFULL + d] = 0.f;
    }
}

// ---------------------------------------------------------------------------
// Stage 1: per-row argmin over 512 codes (f32x2 register-tiled GEMM),
// then per-row outputs (indices, loss, straight-through zq) + atomic
// accumulation of counts and dw segment sums.
// Block: 256 threads = 16(tx along k) x 16(ty along m). Tile: 64 rows.
// ---------------------------------------------------------------------------
__global__ void __launch_bounds__(256, 2)
vq_main(const float* __restrict__ zr, const float* __restrict__ zi,
        const float* __restrict__ emb,
        float* __restrict__ o_zqr, float* __restrict__ o_zqi,
        float* __restrict__ o_loss, float* __restrict__ o_idx)
{
    extern __shared__ char sm[];
    float2* zs    = (float2*)sm;                                   // [64][66]
    float2* wst   = (float2*)(sm + MTILE * ZS_STRIDE * 8);         // [64][128] (dpair-major)
    float*  ysq_s = (float*)(sm + MTILE * ZS_STRIDE * 8 + 64 * 128 * 8); // [128]
    float*  xsq_s = ysq_s + 128;                                   // [64]
    int*    resk  = (int*)(xsq_s + MTILE);                         // [64]

    const int tid  = threadIdx.x;
    const int row0 = blockIdx.x * MTILE;

    // Load z tile: 64 rows x 128 floats (real[0:64] ++ imag[0:64]), coalesced.
    for (int i = tid; i < MTILE * 32; i += 256) {
        int row = i >> 5, q = i & 31;
        const float* src = (q < 16) ? (zr + (size_t)(row0 + row) * DHALF + q * 4)
                                    : (zi + (size_t)(row0 + row) * DHALF + (q - 16) * 4);
        float4 v = *(const float4*)src;
        float2* dst = &zs[row * ZS_STRIDE + q * 2];
        dst[0] = make_float2(v.x, v.y);
        dst[1] = make_float2(v.z, v.w);
    }
    __syncthreads();

    // x_sq per row (sequential fp32, no fma-contraction: square then add)
    if (tid < MTILE) {
        const float* zrow = (const float*)&zs[tid * ZS_STRIDE];
        float s = 0.f;
        #pragma unroll 8
        for (int d = 0; d < DFULL; d++) s = __fadd_rn(s, __fmul_rn(zrow[d], zrow[d]));
        xsq_s[tid] = s;
    }

    const int tx = tid & 15, ty = tid >> 4;
    float bestv[4]; int bestk[4];
    #pragma unroll
    for (int i = 0; i < 4; i++) { bestv[i] = FLT_MAX; bestk[i] = 0; }

    const u64* za = reinterpret_cast<const u64*>(zs) + ty * 4 * ZS_STRIDE;

    for (int c = 0; c < 4; c++) {
        __syncthreads();  // protect wst reuse across chunks
        // Load 128-code chunk transposed: wst[r][k] = (w[k][2r], w[k][2r+1])
        for (int i = tid; i < 64 * 128; i += 256) {
            int r = i >> 7, k = i & 127;
            wst[r * 128 + k] = *(const float2*)(emb + (size_t)(c * 128 + k) * DFULL + r * 2);
        }
        if (tid < 128) ysq_s[tid] = g_ysq[c * 128 + tid];
        __syncthreads();

        u64 acc[4][8];
        #pragma unroll
        for (int i = 0; i < 4; i++)
            #pragma unroll
            for (int j = 0; j < 8; j++) acc[i][j] = 0ull;

        const u64* wa = reinterpret_cast<const u64*>(wst) + tx;
        #pragma unroll 4
        for (int r = 0; r < 64; r++) {
            u64 a0 = za[r];
            u64 a1 = za[r +     ZS_STRIDE];
            u64 a2 = za[r + 2 * ZS_STRIDE];
            u64 a3 = za[r + 3 * ZS_STRIDE];
            const u64* wr = wa + r * 128;
            #pragma unroll
            for (int j = 0; j < 8; j++) {
                u64 b = wr[j * 16];
                acc[0][j] = fma2(a0, b, acc[0][j]);
                acc[1][j] = fma2(a1, b, acc[1][j]);
                acc[2][j] = fma2(a2, b, acc[2][j]);
                acc[3][j] = fma2(a3, b, acc[3][j]);
            }
        }

        // Chunk epilogue: dist = fl(fl(x_sq + y_sq) - 2*dot), strict-< scan
        // (k ascending across c then j -> first-min kept, matching jnp.argmin)
        #pragma unroll
        for (int i = 0; i < 4; i++) {
            float xs = xsq_s[ty * 4 + i];
            #pragma unroll
            for (int j = 0; j < 8; j++) {
                float lo = __uint_as_float((unsigned)(acc[i][j] & 0xffffffffull));
                float hi = __uint_as_float((unsigned)(acc[i][j] >> 32));
                float dot = __fadd_rn(lo, hi);
                float s = __fadd_rn(xs, ysq_s[j * 16 + tx]);
                float dist = __fmaf_rn(-2.0f, dot, s);  // == fl(s - fl(2*dot)), 2*dot exact
                if (dist < bestv[i]) { bestv[i] = dist; bestk[i] = c * 128 + j * 16 + tx; }
            }
        }
    }

    // Cross-tx argmin reduction (16 lanes), tie -> smaller index
    #pragma unroll
    for (int i = 0; i < 4; i++) {
        float v = bestv[i]; int k = bestk[i];
        #pragma unroll
        for (int off = 8; off; off >>= 1) {
            float ov = __shfl_xor_sync(0xffffffffu, v, off);
            int   ok = __shfl_xor_sync(0xffffffffu, k, off);
            if (ov < v || (ov == v && ok < k)) { v = ov; k = ok; }
        }
        if (tx == 0) resk[ty * 4 + i] = k;
    }
    __syncthreads();

    // Phase 2: per-row outputs + segment accumulation. 4 threads per row.
    {
        int row = tid >> 2, part = tid & 3;
        size_t n = (size_t)row0 + row;
        int idx = resk[row];
        const float* wp  = emb + (size_t)idx * DFULL + part * 32;
        const float* zp  = (const float*)&zs[row * ZS_STRIDE] + part * 32;
        float*       dwp = g_dw + (size_t)idx * DFULL + part * 32;
        float* oz = (part < 2) ? (o_zqr + n * DHALF + part * 32)
                               : (o_zqi + n * DHALF + (part - 2) * 32);
        float ls = 0.f;
        #pragma unroll
        for (int q = 0; q < 8; q++) {
            float4 o;
            #pragma unroll
            for (int e = 0; e < 4; e++) {
                float zv = zp[q * 4 + e];
                float wv = __ldg(wp + q * 4 + e);
                float dv = __fsub_rn(wv, zv);
                ls = __fadd_rn(ls, __fmul_rn(dv, dv));
                (&o.x)[e] = __fadd_rn(zv, dv);   // z + (z_q - z): straight-through rounding
                atomicAdd(dwp + q * 4 + e, zv);
            }
            *(float4*)(oz + q * 4) = o;
        }
        ls = __fadd_rn(ls, __shfl_xor_sync(0xffffffffu, ls, 1));
        ls = __fadd_rn(ls, __shfl_xor_sync(0xffffffffu, ls, 2));
        if (part == 0) {
            o_loss[n] = __fmul_rn(0.25f, __fmul_rn(ls, (1.0f / 128.0f)));  // BETA * mean
            o_idx[n]  = (float)idx;
            atomicAdd(&g_nt[idx], 1.0f);
        }
    }
}

// ---------------------------------------------------------------------------
// Stage 2: EMA update, cluster-size normalization, entropy. 1 block x 512.
// ---------------------------------------------------------------------------
__global__ void vq_final(const float* __restrict__ ecs, const float* __restrict__ emaw,
                         float* __restrict__ o_ent, float* __restrict__ o_emb,
                         float* __restrict__ o_nc,  float* __restrict__ o_ema)
{
    __shared__ float red[512];
    int k = threadIdx.x;
    const float DEC = 0.99f;
    const float OM  = (float)(1.0 - 0.99);

    float ntv = g_nt[k];
    float nc  = __fadd_rn(__fmul_rn(ecs[k], DEC), __fmul_rn(OM, ntv));
    o_nc[k] = nc;

    red[k] = nc;
    __syncthreads();
    for (int s = 256; s > 0; s >>= 1) {
        if (k < s) red[k] = __fadd_rn(red[k], red[k + s]);
        __syncthreads();
    }
    float tot = red[0];
    __syncthreads();

    float csz = __fmul_rn(__fdiv_rn(__fadd_rn(nc, 1e-5f),
                                    __fadd_rn(tot, (float)(512 * 1e-5))), tot);

    for (int d = 0; d < DFULL; d++) {
        float ne = __fadd_rn(__fmul_rn(emaw[(size_t)k * DFULL + d], DEC),
                             __fmul_rn(OM, g_dw[(size_t)k * DFULL + d]));
        o_ema[(size_t)k * DFULL + d] = ne;
        o_emb[(size_t)k * DFULL + d] = __fdiv_rn(ne, csz);
    }

    float p = __fdiv_rn(ntv, 262144.0f);
    float t = __fmul_rn(p, logf(__fadd_rn(p, 1e-10f)));
    red[k] = t;
    __syncthreads();
    for (int s = 256; s > 0; s >>= 1) {
        if (k < s) red[k] = __fadd_rn(red[k], red[k + s]);
        __syncthreads();
    }
    if (k == 0) o_ent[0] = __fdiv_rn(-red[0], 6.2383246250395075f);  // / log(512)
}

// ---------------------------------------------------------------------------
extern "C" void kernel_launch(void* const* d_in, const int* in_sizes, int n_in,
                              void* d_out, int out_size)
{
    const float* zr   = (const float*)d_in[0];
    const float* zi   = (const float*)d_in[1];
    const float* emb  = (const float*)d_in[2];
    const float* ecs  = (const float*)d_in[3];
    const float* emaw = (const float*)d_in[4];
    float* out = (float*)d_out;

    size_t nrows = (size_t)in_sizes[0] / DHALF;   // 262144

    // Output layout = reference return tuple, flattened + concatenated
    float* o_zqr  = out;
    float* o_zqi  = o_zqr + nrows * DHALF;
    float* o_loss = o_zqi + nrows * DHALF;
    float* o_idx  = o_loss + nrows;
    float* o_ent  = o_idx + nrows;
    float* o_emb  = o_ent + 1;
    float* o_nc   = o_emb + (size_t)KCODES * DFULL;
    float* o_ema  = o_nc + KCODES;

    vq_prep<<<2, 256>>>(emb);

    const size_t smem = MTILE * ZS_STRIDE * 8   // zs
                      + 64 * 128 * 8            // wst
                      + 128 * 4                 // ysq_s
                      + MTILE * 4               // xsq_s
                      + MTILE * 4;              // resk
    cudaFuncSetAttribute(vq_main, cudaFuncAttributeMaxDynamicSharedMemorySize, (int)smem);
    vq_main<<<(unsigned)(nrows / MTILE), 256, smem>>>(zr, zi, emb,
                                                      o_zqr, o_zqi, o_loss, o_idx);

    vq_final<<<1, 512>>>(ecs, emaw, o_ent, o_emb, o_nc, o_ema);
}